// round 3
// baseline (speedup 1.0000x reference)
#include <cuda_runtime.h>
#include <math.h>

#define N_EL    16
#define N_NUC   4
#define N_FEATS 32
#define N_EN    (N_EL * N_NUC)            // 64
#define N_EE    (N_EL * (N_EL - 1) / 2)   // 120
#define N_PAIRS (N_EN + N_EE)             // 184
#define HIDDEN  64
#define ROWS    128                        // batch rows per CTA
#define THREADS 256
#define CP      4                          // pairs per chunk
#define CK      (CP * N_FEATS)             // 128 k per chunk
#define NCHUNK  (N_PAIRS / CP)             // 46

// ---- shared memory layout (floats) ----
#define OFF_W      0                       // 128*64   = 8192   (W1 chunk / W2)
#define OFF_XS     8192                    // 128*128  = 16384  (xs tile; reused as h1 [128][65])
#define OFF_DISTS  (OFF_XS + 16384)        // 184*128  = 23552
#define OFF_RS     (OFF_DISTS + 23552)     // 128*49   = 6272   (padded stride 49)
#define OFF_MU     (OFF_RS + 6272)         // 32
#define OFF_NIS    (OFF_MU + 32)           // 32
#define OFF_COORD  (OFF_NIS + 32)          // 12
#define OFF_CHG    (OFF_COORD + 12)        // 4
#define OFF_PI     (OFF_CHG + 4)           // 120 (as float-slot ints)
#define OFF_PJ     (OFF_PI + 120)          // 120
#define SMEM_FLOATS (OFF_PJ + 120)
#define SMEM_BYTES  (SMEM_FLOATS * 4)

__device__ __forceinline__ float sspf(float x) {
    // softplus(x) - log(2), numerically stable
    return fmaxf(x, 0.0f) + log1pf(expf(-fabsf(x))) - 0.69314718055994531f;
}

__global__ __launch_bounds__(THREADS, 1)
void wfnet_kernel(const float* __restrict__ rs,
                  const float* __restrict__ coords,
                  const float* __restrict__ charges,
                  const float* __restrict__ W1,
                  const float* __restrict__ b1,
                  const float* __restrict__ W2,
                  const float* __restrict__ b2,
                  const float* __restrict__ W3,
                  const float* __restrict__ b3,
                  float* __restrict__ out)
{
    extern __shared__ float sm[];
    float* s_w     = sm + OFF_W;
    float* s_xs    = sm + OFF_XS;
    float* s_h     = sm + OFF_XS;    // reuse, stride 65
    float* s_dists = sm + OFF_DISTS;
    float* s_rs    = sm + OFF_RS;
    float* s_mu    = sm + OFF_MU;
    float* s_nis   = sm + OFF_NIS;
    float* s_coord = sm + OFF_COORD;
    float* s_chg   = sm + OFF_CHG;
    int*   s_pi    = (int*)(sm + OFF_PI);
    int*   s_pj    = (int*)(sm + OFF_PJ);

    const int tid = threadIdx.x;
    const int b0  = blockIdx.x * ROWS;

    // ---- setup: basis constants, coords, charges, ee pair tables ----
    if (tid < N_FEATS) {
        float q   = (float)tid / 31.0f;
        float mu  = 10.0f * q * q;
        float sig = (1.0f + 10.0f * q) * (1.0f / 7.0f);
        s_mu[tid]  = mu;
        s_nis[tid] = -1.0f / (sig * sig);
    }
    if (tid < 12) s_coord[tid] = coords[tid];
    if (tid < 4)  s_chg[tid]   = charges[tid];
    if (tid < N_EE) {
        int rem = tid, i = 0, span = N_EL - 1;
        while (rem >= span) { rem -= span; span--; i++; }
        s_pi[tid] = i;
        s_pj[tid] = i + 1 + rem;
    }
    // ---- stage rs tile (padded row stride 49 to dodge bank conflicts) ----
    for (int idx = tid; idx < ROWS * 48; idx += THREADS) {
        int row = idx / 48, c = idx % 48;
        s_rs[row * 49 + c] = rs[(size_t)(b0 + row) * 48 + c];
    }
    __syncthreads();

    // ---- all pair distances: s_dists[p][row] ----
    for (int m = tid; m < N_PAIRS * ROWS; m += THREADS) {
        int p = m >> 7, row = m & 127;
        float dx, dy, dz;
        const float* r = s_rs + row * 49;
        if (p < N_EN) {
            int e = p >> 2, a = p & 3;
            dx = r[e * 3 + 0] - s_coord[a * 3 + 0];
            dy = r[e * 3 + 1] - s_coord[a * 3 + 1];
            dz = r[e * 3 + 2] - s_coord[a * 3 + 2];
        } else {
            int q = p - N_EN;
            int i = s_pi[q], j = s_pj[q];
            dx = r[i * 3 + 0] - r[j * 3 + 0];
            dy = r[i * 3 + 1] - r[j * 3 + 1];
            dz = r[i * 3 + 2] - r[j * 3 + 2];
        }
        s_dists[p * ROWS + row] = sqrtf(dx * dx + dy * dy + dz * dz);
    }
    __syncthreads();

    // ---- layer-1 GEMM over 46 chunks of 128 k ----
    const int row  = tid >> 1;
    const int ch32 = (tid & 1) * 32;
    float acc[32];
    #pragma unroll
    for (int j = 0; j < 32; ++j) acc[j] = 0.0f;

    for (int chunk = 0; chunk < NCHUNK; ++chunk) {
        // stage W1 chunk (contiguous 8192 floats)
        const float4* w1g = (const float4*)(W1 + (size_t)chunk * CK * HIDDEN);
        float4* w1s = (float4*)s_w;
        #pragma unroll
        for (int i = 0; i < 8; ++i) w1s[tid + i * THREADS] = w1g[tid + i * THREADS];

        // materialize xs tile: s_xs[k][row], k = p_local*32 + f
        const int pbase = chunk * CP;
        #pragma unroll
        for (int i = 0; i < (CK * ROWS) / THREADS; ++i) {
            int idx = tid + i * THREADS;
            int r2  = idx & 127;
            int k   = idx >> 7;
            int f   = k & 31;
            int p   = pbase + (k >> 5);
            float d  = s_dists[p * ROWS + r2];
            float t  = d - s_mu[f];
            s_xs[k * ROWS + r2] = __expf(t * t * s_nis[f]);
        }
        __syncthreads();

        const float* xcol = s_xs + row;
        #pragma unroll 2
        for (int k = 0; k < CK; ++k) {
            float a = xcol[k * ROWS];
            const float4* w4 = (const float4*)(s_w + k * HIDDEN + ch32);
            #pragma unroll
            for (int jj = 0; jj < 8; ++jj) {
                float4 w = w4[jj];
                acc[4 * jj + 0] += a * w.x;
                acc[4 * jj + 1] += a * w.y;
                acc[4 * jj + 2] += a * w.z;
                acc[4 * jj + 3] += a * w.w;
            }
        }
        __syncthreads();
    }

    // ---- bias + ssp -> s_h (stride 65); stage W2 ----
    for (int i = tid; i < HIDDEN * HIDDEN; i += THREADS) s_w[i] = W2[i];
    #pragma unroll
    for (int jj = 0; jj < 32; ++jj) {
        float v = acc[jj] + b1[ch32 + jj];
        s_h[row * 65 + ch32 + jj] = sspf(v);
    }
    __syncthreads();

    // ---- layer 2 + layer 3 partial ----
    float acc2[32];
    #pragma unroll
    for (int j = 0; j < 32; ++j) acc2[j] = 0.0f;
    const float* hrow = s_h + row * 65;
    #pragma unroll 2
    for (int k = 0; k < HIDDEN; ++k) {
        float a = hrow[k];
        const float4* w4 = (const float4*)(s_w + k * HIDDEN + ch32);
        #pragma unroll
        for (int jj = 0; jj < 8; ++jj) {
            float4 w = w4[jj];
            acc2[4 * jj + 0] += a * w.x;
            acc2[4 * jj + 1] += a * w.y;
            acc2[4 * jj + 2] += a * w.z;
            acc2[4 * jj + 3] += a * w.w;
        }
    }
    float partial = 0.0f;
    #pragma unroll
    for (int jj = 0; jj < 32; ++jj) {
        float h2 = sspf(acc2[jj] + b2[ch32 + jj]);
        partial += h2 * W3[ch32 + jj];
    }
    float other = __shfl_xor_sync(0xffffffffu, partial, 1);
    float ys = partial + other + b3[0];

    // ---- asymptotic factor + output (one thread per row) ----
    if ((tid & 1) == 0) {
        float S = 0.0f;
        #pragma unroll 4
        for (int p = 0; p < N_EN; ++p) {
            float d = s_dists[p * ROWS + row];
            float Z = s_chg[p & 3];
            // decay = sqrt(2*0.5) = 1, ALPHA = 1
            S += (Z * d + d * d) / (1.0f + d);
        }
        out[b0 + row] = expf(ys) * expf(-S);
    }
}

extern "C" void kernel_launch(void* const* d_in, const int* in_sizes, int n_in,
                              void* d_out, int out_size)
{
    const float* rs      = (const float*)d_in[0];
    const float* coords  = (const float*)d_in[1];
    const float* charges = (const float*)d_in[2];
    const float* W1      = (const float*)d_in[3];
    const float* b1      = (const float*)d_in[4];
    const float* W2      = (const float*)d_in[5];
    const float* b2      = (const float*)d_in[6];
    const float* W3      = (const float*)d_in[7];
    const float* b3      = (const float*)d_in[8];
    float* out = (float*)d_out;

    int batch = in_sizes[0] / (N_EL * 3);
    int grid  = batch / ROWS;

    cudaFuncSetAttribute(wfnet_kernel,
                         cudaFuncAttributeMaxDynamicSharedMemorySize, SMEM_BYTES);
    wfnet_kernel<<<grid, THREADS, SMEM_BYTES>>>(rs, coords, charges,
                                                W1, b1, W2, b2, W3, b3, out);
}

// round 4
// speedup vs baseline: 1.0790x; 1.0790x over previous
#include <cuda_runtime.h>
#include <math.h>
#include <stdint.h>

#define N_EL    16
#define N_NUC   4
#define N_FEATS 32
#define N_EN    (N_EL * N_NUC)            // 64
#define N_EE    (N_EL * (N_EL - 1) / 2)   // 120
#define N_PAIRS (N_EN + N_EE)             // 184
#define HIDDEN  64
#define ROWS    256                        // batch rows per CTA
#define THREADS 256
#define CK      64                         // k per chunk (2 pairs x 32 feats)
#define NCHUNK  (N_PAIRS * N_FEATS / CK)   // 92

// ---- shared memory layout (float slots) ----
#define OFF_WD    0                        // u64[4096] = 8192 floats (W1 chunk dup'd / W2)
#define OFF_XS    8192                     // 64*256 = 16384
#define OFF_RS    (OFF_XS + 16384)         // 256*49 = 12544 (padded stride 49)
#define OFF_H     (OFF_RS + 12544)         // 256*66 = 16896
#define OFF_MU    (OFF_H + 16896)          // 32
#define OFF_NIS   (OFF_MU + 32)            // 32
#define OFF_COORD (OFF_NIS + 32)           // 12
#define OFF_CHG   (OFF_COORD + 12)         // 4
#define OFF_B1    (OFF_CHG + 4)            // 64
#define OFF_B2    (OFF_B1 + 64)            // 64
#define OFF_W3    (OFF_B2 + 64)            // 64
#define OFF_B3    (OFF_W3 + 64)            // 4 (1 + pad)
#define OFF_PI    (OFF_B3 + 4)             // 120 (ints in float slots)
#define OFF_PJ    (OFF_PI + 120)           // 120
#define SMEM_FLOATS (OFF_PJ + 120)         // 54532
#define SMEM_BYTES  (SMEM_FLOATS * 4)      // ~218 KB

__device__ __forceinline__ float sspf(float x) {
    // softplus(x) - log(2), numerically stable
    return fmaxf(x, 0.0f) + log1pf(expf(-fabsf(x))) - 0.69314718055994531f;
}

// packed dual-fp32 FMA: d.lo += a.lo*b.lo ; d.hi += a.hi*b.hi
__device__ __forceinline__ void fma2(unsigned long long& d,
                                     unsigned long long a,
                                     unsigned long long b) {
    asm("fma.rn.f32x2 %0, %1, %2, %0;" : "+l"(d) : "l"(a), "l"(b));
}

__device__ __forceinline__ unsigned long long dup2(float v) {
    unsigned long long r;
    unsigned u = __float_as_uint(v);
    asm("mov.b64 %0, {%1, %1};" : "=l"(r) : "r"(u));
    return r;
}

__global__ __launch_bounds__(THREADS, 1)
void wfnet_kernel(const float* __restrict__ rs,
                  const float* __restrict__ coords,
                  const float* __restrict__ charges,
                  const float* __restrict__ W1,
                  const float* __restrict__ b1,
                  const float* __restrict__ W2,
                  const float* __restrict__ b2,
                  const float* __restrict__ W3,
                  const float* __restrict__ b3,
                  float* __restrict__ out)
{
    extern __shared__ float sm[];
    unsigned long long* s_wd = (unsigned long long*)(sm + OFF_WD);
    float* s_xs    = sm + OFF_XS;
    float* s_rs    = sm + OFF_RS;
    float* s_h     = sm + OFF_H;
    float* s_mu    = sm + OFF_MU;
    float* s_nis   = sm + OFF_NIS;
    float* s_coord = sm + OFF_COORD;
    float* s_chg   = sm + OFF_CHG;
    float* s_b1    = sm + OFF_B1;
    float* s_b2    = sm + OFF_B2;
    float* s_w3    = sm + OFF_W3;
    float* s_b3    = sm + OFF_B3;
    int*   s_pi    = (int*)(sm + OFF_PI);
    int*   s_pj    = (int*)(sm + OFF_PJ);

    const int tid = threadIdx.x;
    const int b0  = blockIdx.x * ROWS;
    const int tx  = tid & 7;     // col group: cols tx*8 .. tx*8+7
    const int ty  = tid >> 3;    // row group: rows ty*8 .. ty*8+7 (0..31)

    // ---- setup ----
    if (tid < N_FEATS) {
        float q   = (float)tid / 31.0f;
        float mu  = 10.0f * q * q;
        float sig = (1.0f + 10.0f * q) * (1.0f / 7.0f);
        s_mu[tid]  = mu;
        s_nis[tid] = -1.0f / (sig * sig);
    }
    if (tid < 12) s_coord[tid] = coords[tid];
    if (tid < 4)  s_chg[tid]   = charges[tid];
    if (tid < HIDDEN) {
        s_b1[tid] = b1[tid];
        s_b2[tid] = b2[tid];
        s_w3[tid] = W3[tid];
    }
    if (tid == 0) s_b3[0] = b3[0];
    if (tid < N_EE) {
        int rem = tid, i = 0, span = N_EL - 1;
        while (rem >= span) { rem -= span; span--; i++; }
        s_pi[tid] = i;
        s_pj[tid] = i + 1 + rem;
    }
    // stage rs tile (padded stride 49)
    for (int idx = tid; idx < ROWS * 48; idx += THREADS) {
        int row = idx / 48, c = idx % 48;
        s_rs[row * 49 + c] = rs[(size_t)(b0 + row) * 48 + c];
    }
    __syncthreads();

    const float* myr = s_rs + tid * 49;   // this thread's row (row = tid)

    // ---- layer-1 GEMM: acc[row-pair][col], f32x2 packed across row pairs ----
    unsigned long long acc[4][8];
    #pragma unroll
    for (int rp = 0; rp < 4; ++rp)
        #pragma unroll
        for (int c = 0; c < 8; ++c) acc[rp][c] = 0ull;

    for (int chunk = 0; chunk < NCHUNK; ++chunk) {
        // my two pair distances for this chunk (row = tid)
        float dloc[2];
        #pragma unroll
        for (int pl = 0; pl < 2; ++pl) {
            int p = chunk * 2 + pl;
            float dx, dy, dz;
            if (p < N_EN) {
                int e = p >> 2, a = p & 3;
                dx = myr[e * 3 + 0] - s_coord[a * 3 + 0];
                dy = myr[e * 3 + 1] - s_coord[a * 3 + 1];
                dz = myr[e * 3 + 2] - s_coord[a * 3 + 2];
            } else {
                int q = p - N_EN;
                int i = s_pi[q], j = s_pj[q];
                dx = myr[i * 3 + 0] - myr[j * 3 + 0];
                dy = myr[i * 3 + 1] - myr[j * 3 + 1];
                dz = myr[i * 3 + 2] - myr[j * 3 + 2];
            }
            dloc[pl] = sqrtf(dx * dx + dy * dy + dz * dz);
        }

        __syncthreads();   // prior GEMM done reading s_wd / s_xs

        // stage W1 chunk, duplicated into f32x2 lanes: s_wd[k*64+c] = (w,w)
        {
            const float4* wg = (const float4*)(W1 + (size_t)chunk * CK * HIDDEN);
            #pragma unroll
            for (int i = 0; i < 4; ++i) {
                float4 v = wg[tid + i * THREADS];
                int j = (tid + i * THREADS) * 4;
                s_wd[j + 0] = dup2(v.x);
                s_wd[j + 1] = dup2(v.y);
                s_wd[j + 2] = dup2(v.z);
                s_wd[j + 3] = dup2(v.w);
            }
        }
        // materialize xs tile: s_xs[k][row], row = tid
        #pragma unroll
        for (int i = 0; i < CK; ++i) {
            int f = i & 31;
            float d = dloc[i >> 5];
            float t = d - s_mu[f];
            s_xs[i * ROWS + tid] = __expf(t * t * s_nis[f]);
        }
        __syncthreads();

        // 128x64x64 SMEM GEMM, 8x8 per thread, f32x2 packed over row pairs
        #pragma unroll 2
        for (int k = 0; k < CK; ++k) {
            const float* xb = s_xs + k * ROWS + ty * 8;
            ulonglong2 xa = *(const ulonglong2*)(xb);
            ulonglong2 xc = *(const ulonglong2*)(xb + 4);
            unsigned long long xr[4] = { xa.x, xa.y, xc.x, xc.y };

            const ulonglong2* wb = (const ulonglong2*)(s_wd + k * HIDDEN + tx * 8);
            ulonglong2 w0 = wb[0], w1 = wb[1], w2 = wb[2], w3v = wb[3];
            unsigned long long wr[8] = { w0.x, w0.y, w1.x, w1.y,
                                         w2.x, w2.y, w3v.x, w3v.y };
            #pragma unroll
            for (int c = 0; c < 8; ++c) {
                fma2(acc[0][c], xr[0], wr[c]);
                fma2(acc[1][c], xr[1], wr[c]);
                fma2(acc[2][c], xr[2], wr[c]);
                fma2(acc[3][c], xr[3], wr[c]);
            }
        }
    }
    __syncthreads();   // GEMM fully done; s_wd reusable

    // ---- stage W2 (as plain floats over s_wd area) + epilogue ssp -> s_h ----
    float* s_w2 = (float*)s_wd;
    for (int i = tid; i < HIDDEN * HIDDEN; i += THREADS) s_w2[i] = W2[i];

    #pragma unroll
    for (int rp = 0; rp < 4; ++rp) {
        int r0 = ty * 8 + rp * 2;
        #pragma unroll
        for (int c = 0; c < 8; ++c) {
            int col = tx * 8 + c;
            unsigned long long v = acc[rp][c];
            float lo = __uint_as_float((unsigned)(v & 0xffffffffull));
            float hi = __uint_as_float((unsigned)(v >> 32));
            float bb = s_b1[col];
            s_h[(r0 + 0) * 66 + col] = sspf(lo + bb);
            s_h[(r0 + 1) * 66 + col] = sspf(hi + bb);
        }
    }
    __syncthreads();

    // ---- layer 2 (thread = row), layer 3, asymp ----
    float a2[HIDDEN];
    #pragma unroll
    for (int c = 0; c < HIDDEN; ++c) a2[c] = 0.0f;
    const float* hrow = s_h + tid * 66;
    #pragma unroll 2
    for (int k = 0; k < HIDDEN; ++k) {
        float a = hrow[k];
        const float4* w4 = (const float4*)(s_w2 + k * HIDDEN);
        #pragma unroll
        for (int j = 0; j < 16; ++j) {
            float4 w = w4[j];
            a2[4 * j + 0] += a * w.x;
            a2[4 * j + 1] += a * w.y;
            a2[4 * j + 2] += a * w.z;
            a2[4 * j + 3] += a * w.w;
        }
    }
    float partial = 0.0f;
    #pragma unroll
    for (int c = 0; c < HIDDEN; ++c)
        partial += sspf(a2[c] + s_b2[c]) * s_w3[c];
    float ys = partial + s_b3[0];

    float S = 0.0f;
    #pragma unroll 4
    for (int e = 0; e < N_EL; ++e) {
        float ex = myr[e * 3 + 0], ey = myr[e * 3 + 1], ez = myr[e * 3 + 2];
        #pragma unroll
        for (int a = 0; a < N_NUC; ++a) {
            float dx = ex - s_coord[a * 3 + 0];
            float dy = ey - s_coord[a * 3 + 1];
            float dz = ez - s_coord[a * 3 + 2];
            float d  = sqrtf(dx * dx + dy * dy + dz * dz);
            // decay = sqrt(2*0.5) = 1, ALPHA = 1
            S += (s_chg[a] * d + d * d) / (1.0f + d);
        }
    }
    out[b0 + tid] = expf(ys) * expf(-S);
}

extern "C" void kernel_launch(void* const* d_in, const int* in_sizes, int n_in,
                              void* d_out, int out_size)
{
    const float* rs      = (const float*)d_in[0];
    const float* coords  = (const float*)d_in[1];
    const float* charges = (const float*)d_in[2];
    const float* W1      = (const float*)d_in[3];
    const float* b1      = (const float*)d_in[4];
    const float* W2      = (const float*)d_in[5];
    const float* b2      = (const float*)d_in[6];
    const float* W3      = (const float*)d_in[7];
    const float* b3      = (const float*)d_in[8];
    float* out = (float*)d_out;

    int batch = in_sizes[0] / (N_EL * 3);
    int grid  = batch / ROWS;

    cudaFuncSetAttribute(wfnet_kernel,
                         cudaFuncAttributeMaxDynamicSharedMemorySize, SMEM_BYTES);
    wfnet_kernel<<<grid, THREADS, SMEM_BYTES>>>(rs, coords, charges,
                                                W1, b1, W2, b2, W3, b3, out);
}

// round 5
// speedup vs baseline: 2.9026x; 2.6899x over previous
#include <cuda_runtime.h>
#include <math.h>
#include <stdint.h>

#define N_EL    16
#define N_NUC   4
#define N_FEATS 32
#define N_EN    (N_EL * N_NUC)            // 64
#define N_EE    (N_EL * (N_EL - 1) / 2)   // 120
#define N_PAIRS (N_EN + N_EE)             // 184
#define HIDDEN  64
#define ROWS    256                        // batch rows per CTA
#define THREADS 256
#define CK      64                         // k per chunk (2 pairs x 32 feats)
#define NCHUNK  (N_PAIRS * N_FEATS / CK)   // 92

// ---- shared memory layout (float slots) ----
#define OFF_W     0                        // 64*64 = 4096 (W1 chunk plain / W2)
#define OFF_XS    4096                     // 64*256 = 16384
#define OFF_RS    (OFF_XS + 16384)         // 256*49 = 12544 (padded stride 49)
#define OFF_H     (OFF_RS + 12544)         // 256*66 = 16896
#define OFF_MU    (OFF_H + 16896)          // 32
#define OFF_NIS   (OFF_MU + 32)            // 32
#define OFF_COORD (OFF_NIS + 32)           // 12
#define OFF_CHG   (OFF_COORD + 12)         // 4
#define OFF_B1    (OFF_CHG + 4)            // 64
#define OFF_B2    (OFF_B1 + 64)            // 64
#define OFF_W3    (OFF_B2 + 64)            // 64
#define OFF_B3    (OFF_W3 + 64)            // 4
#define OFF_PI    (OFF_B3 + 4)             // 120
#define OFF_PJ    (OFF_PI + 120)           // 120
#define SMEM_FLOATS (OFF_PJ + 120)
#define SMEM_BYTES  (SMEM_FLOATS * 4)      // ~202 KB

__device__ __forceinline__ float sspf(float x) {
    return fmaxf(x, 0.0f) + log1pf(expf(-fabsf(x))) - 0.69314718055994531f;
}

// packed dual-fp32 FMA: d.lo += a.lo*b.lo ; d.hi += a.hi*b.hi
__device__ __forceinline__ void fma2(unsigned long long& d,
                                     unsigned long long a,
                                     unsigned long long b) {
    asm("fma.rn.f32x2 %0, %1, %2, %0;" : "+l"(d) : "l"(a), "l"(b));
}

__device__ __forceinline__ unsigned long long dup2(float v) {
    unsigned long long r;
    unsigned u = __float_as_uint(v);
    asm("mov.b64 %0, {%1, %1};" : "=l"(r) : "r"(u));
    return r;
}

__global__ __launch_bounds__(THREADS, 1)
void wfnet_kernel(const float* __restrict__ rs,
                  const float* __restrict__ coords,
                  const float* __restrict__ charges,
                  const float* __restrict__ W1,
                  const float* __restrict__ b1,
                  const float* __restrict__ W2,
                  const float* __restrict__ b2,
                  const float* __restrict__ W3,
                  const float* __restrict__ b3,
                  float* __restrict__ out)
{
    extern __shared__ float sm[];
    float* s_w     = sm + OFF_W;
    float* s_xs    = sm + OFF_XS;
    float* s_rs    = sm + OFF_RS;
    float* s_h     = sm + OFF_H;
    float* s_mu    = sm + OFF_MU;
    float* s_nis   = sm + OFF_NIS;
    float* s_coord = sm + OFF_COORD;
    float* s_chg   = sm + OFF_CHG;
    float* s_b1    = sm + OFF_B1;
    float* s_b2    = sm + OFF_B2;
    float* s_w3    = sm + OFF_W3;
    float* s_b3    = sm + OFF_B3;
    int*   s_pi    = (int*)(sm + OFF_PI);
    int*   s_pj    = (int*)(sm + OFF_PJ);

    const int tid = threadIdx.x;
    const int b0  = blockIdx.x * ROWS;
    const int tx  = tid & 7;     // col group: cols tx*8 .. tx*8+7
    const int ty  = tid >> 3;    // row group: rows ty*8 .. ty*8+7 (0..31)

    // ---- setup ----
    if (tid < N_FEATS) {
        float q   = (float)tid / 31.0f;
        float mu  = 10.0f * q * q;
        float sig = (1.0f + 10.0f * q) * (1.0f / 7.0f);
        s_mu[tid]  = mu;
        s_nis[tid] = -1.0f / (sig * sig);
    }
    if (tid < 12) s_coord[tid] = coords[tid];
    if (tid < 4)  s_chg[tid]   = charges[tid];
    if (tid < HIDDEN) {
        s_b1[tid] = b1[tid];
        s_b2[tid] = b2[tid];
        s_w3[tid] = W3[tid];
    }
    if (tid == 0) s_b3[0] = b3[0];
    if (tid < N_EE) {
        int rem = tid, i = 0, span = N_EL - 1;
        while (rem >= span) { rem -= span; span--; i++; }
        s_pi[tid] = i;
        s_pj[tid] = i + 1 + rem;
    }
    for (int idx = tid; idx < ROWS * 48; idx += THREADS) {
        int row = idx / 48, c = idx % 48;
        s_rs[row * 49 + c] = rs[(size_t)(b0 + row) * 48 + c];
    }
    __syncthreads();

    const float* myr = s_rs + tid * 49;   // this thread's row (row = tid)

    // ---- layer-1 GEMM: acc[row-pair][col], f32x2 packed across row pairs ----
    unsigned long long acc[4][8];
    #pragma unroll
    for (int rp = 0; rp < 4; ++rp)
        #pragma unroll
        for (int c = 0; c < 8; ++c) acc[rp][c] = 0ull;

    for (int chunk = 0; chunk < NCHUNK; ++chunk) {
        // prefetch W1 chunk into regs (L2 latency hides under dist compute)
        float4 wreg[4];
        {
            const float4* wg = (const float4*)(W1 + (size_t)chunk * CK * HIDDEN);
            #pragma unroll
            for (int i = 0; i < 4; ++i) wreg[i] = wg[tid + i * THREADS];
        }

        // my two pair distances for this chunk (row = tid)
        float dloc[2];
        #pragma unroll
        for (int pl = 0; pl < 2; ++pl) {
            int p = chunk * 2 + pl;
            float dx, dy, dz;
            if (p < N_EN) {
                int e = p >> 2, a = p & 3;
                dx = myr[e * 3 + 0] - s_coord[a * 3 + 0];
                dy = myr[e * 3 + 1] - s_coord[a * 3 + 1];
                dz = myr[e * 3 + 2] - s_coord[a * 3 + 2];
            } else {
                int q = p - N_EN;
                int i = s_pi[q], j = s_pj[q];
                dx = myr[i * 3 + 0] - myr[j * 3 + 0];
                dy = myr[i * 3 + 1] - myr[j * 3 + 1];
                dz = myr[i * 3 + 2] - myr[j * 3 + 2];
            }
            dloc[pl] = sqrtf(dx * dx + dy * dy + dz * dz);
        }

        __syncthreads();   // prior GEMM done reading s_w / s_xs

        // stage W1 chunk (plain, conflict-light) + xs tile
        {
            float4* ws = (float4*)s_w;
            #pragma unroll
            for (int i = 0; i < 4; ++i) ws[tid + i * THREADS] = wreg[i];
        }
        #pragma unroll
        for (int i = 0; i < CK; ++i) {
            int f = i & 31;
            float d = dloc[i >> 5];
            float t = d - s_mu[f];
            s_xs[i * ROWS + tid] = __expf(t * t * s_nis[f]);
        }
        __syncthreads();

        // 256x64x64 SMEM GEMM, 8x8 per thread, f32x2 over row pairs;
        // W read plain (32 B/thread/k), duplicated into lanes in registers.
        #pragma unroll 2
        for (int k = 0; k < CK; ++k) {
            const float* xb = s_xs + k * ROWS + ty * 8;
            ulonglong2 xa = *(const ulonglong2*)(xb);
            ulonglong2 xc = *(const ulonglong2*)(xb + 4);
            unsigned long long xr[4] = { xa.x, xa.y, xc.x, xc.y };

            const float4* wb = (const float4*)(s_w + k * HIDDEN + tx * 8);
            float4 w0 = wb[0], w1 = wb[1];
            unsigned long long wr[8] = {
                dup2(w0.x), dup2(w0.y), dup2(w0.z), dup2(w0.w),
                dup2(w1.x), dup2(w1.y), dup2(w1.z), dup2(w1.w)
            };
            #pragma unroll
            for (int c = 0; c < 8; ++c) {
                fma2(acc[0][c], xr[0], wr[c]);
                fma2(acc[1][c], xr[1], wr[c]);
                fma2(acc[2][c], xr[2], wr[c]);
                fma2(acc[3][c], xr[3], wr[c]);
            }
        }
    }
    __syncthreads();   // GEMM fully done; s_w reusable

    // ---- stage W2 + epilogue ssp -> s_h ----
    for (int i = tid; i < HIDDEN * HIDDEN; i += THREADS) s_w[i] = W2[i];

    #pragma unroll
    for (int rp = 0; rp < 4; ++rp) {
        int r0 = ty * 8 + rp * 2;
        #pragma unroll
        for (int c = 0; c < 8; ++c) {
            int col = tx * 8 + c;
            unsigned long long v = acc[rp][c];
            float lo = __uint_as_float((unsigned)(v & 0xffffffffull));
            float hi = __uint_as_float((unsigned)(v >> 32));
            float bb = s_b1[col];
            s_h[(r0 + 0) * 66 + col] = sspf(lo + bb);
            s_h[(r0 + 1) * 66 + col] = sspf(hi + bb);
        }
    }
    __syncthreads();

    // ---- layer 2 (thread = row), layer 3, asymp ----
    float a2[HIDDEN];
    #pragma unroll
    for (int c = 0; c < HIDDEN; ++c) a2[c] = 0.0f;
    const float* hrow = s_h + tid * 66;
    #pragma unroll 2
    for (int k = 0; k < HIDDEN; ++k) {
        float a = hrow[k];
        const float4* w4 = (const float4*)(s_w + k * HIDDEN);
        #pragma unroll
        for (int j = 0; j < 16; ++j) {
            float4 w = w4[j];
            a2[4 * j + 0] += a * w.x;
            a2[4 * j + 1] += a * w.y;
            a2[4 * j + 2] += a * w.z;
            a2[4 * j + 3] += a * w.w;
        }
    }
    float partial = 0.0f;
    #pragma unroll
    for (int c = 0; c < HIDDEN; ++c)
        partial += sspf(a2[c] + s_b2[c]) * s_w3[c];
    float ys = partial + s_b3[0];

    float S = 0.0f;
    #pragma unroll 4
    for (int e = 0; e < N_EL; ++e) {
        float ex = myr[e * 3 + 0], ey = myr[e * 3 + 1], ez = myr[e * 3 + 2];
        #pragma unroll
        for (int a = 0; a < N_NUC; ++a) {
            float dx = ex - s_coord[a * 3 + 0];
            float dy = ey - s_coord[a * 3 + 1];
            float dz = ez - s_coord[a * 3 + 2];
            float d  = sqrtf(dx * dx + dy * dy + dz * dz);
            S += (s_chg[a] * d + d * d) / (1.0f + d);
        }
    }
    out[b0 + tid] = expf(ys) * expf(-S);
}

extern "C" void kernel_launch(void* const* d_in, const int* in_sizes, int n_in,
                              void* d_out, int out_size)
{
    const float* rs      = (const float*)d_in[0];
    const float* coords  = (const float*)d_in[1];
    const float* charges = (const float*)d_in[2];
    const float* W1      = (const float*)d_in[3];
    const float* b1      = (const float*)d_in[4];
    const float* W2      = (const float*)d_in[5];
    const float* b2      = (const float*)d_in[6];
    const float* W3      = (const float*)d_in[7];
    const float* b3      = (const float*)d_in[8];
    float* out = (float*)d_out;

    int batch = in_sizes[0] / (N_EL * 3);
    int grid  = batch / ROWS;

    cudaFuncSetAttribute(wfnet_kernel,
                         cudaFuncAttributeMaxDynamicSharedMemorySize, SMEM_BYTES);
    wfnet_kernel<<<grid, THREADS, SMEM_BYTES>>>(rs, coords, charges,
                                                W1, b1, W2, b2, W3, b3, out);
}

// round 6
// speedup vs baseline: 3.0259x; 1.0425x over previous
#include <cuda_runtime.h>
#include <math.h>
#include <stdint.h>

#define N_EL    16
#define N_NUC   4
#define N_FEATS 32
#define N_EN    (N_EL * N_NUC)            // 64
#define N_EE    (N_EL * (N_EL - 1) / 2)   // 120
#define N_PAIRS (N_EN + N_EE)             // 184
#define HIDDEN  64
#define ROWS    256                        // batch rows per CTA
#define THREADS 256
#define CK      64                         // k per chunk (2 pairs x 32 feats)
#define NCHUNK  (N_PAIRS * N_FEATS / CK)   // 92

// ---- shared memory layout (float slots) ----
#define OFF_W     0                        // 2 x 64*64 = 8192 (W1 chunk ping-pong / W2)
#define OFF_XS    8192                     // 2 x 64*256 = 32768 (xs ping-pong; reused as h)
#define OFF_RS    (OFF_XS + 32768)         // 256*49 = 12544 (padded stride 49)
#define OFF_A     (OFF_RS + 12544)         // 32
#define OFF_Bc    (OFF_A + 32)             // 32
#define OFF_Cc    (OFF_Bc + 32)            // 32
#define OFF_COORD (OFF_Cc + 32)            // 12
#define OFF_CHG   (OFF_COORD + 12)         // 4
#define OFF_B1    (OFF_CHG + 4)            // 64
#define OFF_B2    (OFF_B1 + 64)            // 64
#define OFF_W3    (OFF_B2 + 64)            // 64
#define OFF_B3    (OFF_W3 + 64)            // 4
#define OFF_PI    (OFF_B3 + 4)             // 120
#define OFF_PJ    (OFF_PI + 120)           // 120
#define SMEM_FLOATS (OFF_PJ + 120)
#define SMEM_BYTES  (SMEM_FLOATS * 4)      // ~216 KB

#define LOG2E 1.4426950408889634f

__device__ __forceinline__ float sspf(float x) {
    return fmaxf(x, 0.0f) + log1pf(expf(-fabsf(x))) - 0.69314718055994531f;
}

// packed dual-fp32 FMA: d.lo += a.lo*b.lo ; d.hi += a.hi*b.hi
__device__ __forceinline__ void fma2(unsigned long long& d,
                                     unsigned long long a,
                                     unsigned long long b) {
    asm("fma.rn.f32x2 %0, %1, %2, %0;" : "+l"(d) : "l"(a), "l"(b));
}

__device__ __forceinline__ unsigned long long dup2(float v) {
    unsigned long long r;
    unsigned u = __float_as_uint(v);
    asm("mov.b64 %0, {%1, %1};" : "=l"(r) : "r"(u));
    return r;
}

__device__ __forceinline__ float ex2(float x) {
    float r;
    asm("ex2.approx.ftz.f32 %0, %1;" : "=f"(r) : "f"(x));
    return r;
}

__global__ __launch_bounds__(THREADS, 1)
void wfnet_kernel(const float* __restrict__ rs,
                  const float* __restrict__ coords,
                  const float* __restrict__ charges,
                  const float* __restrict__ W1,
                  const float* __restrict__ b1,
                  const float* __restrict__ W2,
                  const float* __restrict__ b2,
                  const float* __restrict__ W3,
                  const float* __restrict__ b3,
                  float* __restrict__ out)
{
    extern __shared__ float sm[];
    float* s_w     = sm + OFF_W;      // two 4096-float buffers
    float* s_xs    = sm + OFF_XS;     // two 16384-float buffers
    float* s_rs    = sm + OFF_RS;
    float* s_h     = sm + OFF_XS;     // overlay after GEMM, stride 66
    float* s_A     = sm + OFF_A;
    float* s_B     = sm + OFF_Bc;
    float* s_C     = sm + OFF_Cc;
    float* s_coord = sm + OFF_COORD;
    float* s_chg   = sm + OFF_CHG;
    float* s_b1    = sm + OFF_B1;
    float* s_b2    = sm + OFF_B2;
    float* s_w3    = sm + OFF_W3;
    float* s_b3    = sm + OFF_B3;
    int*   s_pi    = (int*)(sm + OFF_PI);
    int*   s_pj    = (int*)(sm + OFF_PJ);

    const int tid = threadIdx.x;
    const int b0  = blockIdx.x * ROWS;
    const int tx  = tid & 7;     // col group: cols tx*8 .. tx*8+7
    const int ty  = tid >> 3;    // row group: rows ty*8 .. ty*8+7 (0..31)

    // ---- setup ----
    if (tid < N_FEATS) {
        float q   = (float)tid / 31.0f;
        float mu  = 10.0f * q * q;
        float sig = (1.0f + 10.0f * q) * (1.0f / 7.0f);
        float a   = -LOG2E / (sig * sig);       // exp2 coefficient
        s_A[tid] = a;
        s_B[tid] = -2.0f * mu * a;
        s_C[tid] = a * mu * mu;
    }
    if (tid < 12) s_coord[tid] = coords[tid];
    if (tid < 4)  s_chg[tid]   = charges[tid];
    if (tid < HIDDEN) {
        s_b1[tid] = b1[tid];
        s_b2[tid] = b2[tid];
        s_w3[tid] = W3[tid];
    }
    if (tid == 0) s_b3[0] = b3[0];
    if (tid < N_EE) {
        int rem = tid, i = 0, span = N_EL - 1;
        while (rem >= span) { rem -= span; span--; i++; }
        s_pi[tid] = i;
        s_pj[tid] = i + 1 + rem;
    }
    for (int idx = tid; idx < ROWS * 48; idx += THREADS) {
        int row = idx / 48, c = idx % 48;
        s_rs[row * 49 + c] = rs[(size_t)(b0 + row) * 48 + c];
    }
    __syncthreads();

    const float* myr = s_rs + tid * 49;   // this thread's row (row = tid)

    // ---- compute the two pair distances for a chunk ----
    auto chunk_dists = [&](int chunk, float dloc[2]) {
        #pragma unroll
        for (int pl = 0; pl < 2; ++pl) {
            int p = chunk * 2 + pl;
            float dx, dy, dz;
            if (p < N_EN) {
                int e = p >> 2, a = p & 3;
                dx = myr[e * 3 + 0] - s_coord[a * 3 + 0];
                dy = myr[e * 3 + 1] - s_coord[a * 3 + 1];
                dz = myr[e * 3 + 2] - s_coord[a * 3 + 2];
            } else {
                int q = p - N_EN;
                int i = s_pi[q], j = s_pj[q];
                dx = myr[i * 3 + 0] - myr[j * 3 + 0];
                dy = myr[i * 3 + 1] - myr[j * 3 + 1];
                dz = myr[i * 3 + 2] - myr[j * 3 + 2];
            }
            dloc[pl] = sqrtf(dx * dx + dy * dy + dz * dz);
        }
    };

    auto stage_xs = [&](int chunk, float* xs_dst) {
        float dloc[2];
        chunk_dists(chunk, dloc);
        #pragma unroll
        for (int i = 0; i < CK; ++i) {
            int f = i & 31;
            float d = dloc[i >> 5];
            float e = fmaf(fmaf(d, s_A[f], s_B[f]), d, s_C[f]);
            xs_dst[i * ROWS + tid] = ex2(e);
        }
    };

    // ---- prologue: stage chunk 0 into buffer 0 ----
    {
        float4 wreg[4];
        const float4* wg = (const float4*)W1;
        #pragma unroll
        for (int i = 0; i < 4; ++i) wreg[i] = wg[tid + i * THREADS];
        stage_xs(0, s_xs);
        float4* ws = (float4*)s_w;
        #pragma unroll
        for (int i = 0; i < 4; ++i) ws[tid + i * THREADS] = wreg[i];
    }
    __syncthreads();

    // ---- layer-1 GEMM, double-buffered, one barrier per chunk ----
    unsigned long long acc[4][8];
    #pragma unroll
    for (int rp = 0; rp < 4; ++rp)
        #pragma unroll
        for (int c = 0; c < 8; ++c) acc[rp][c] = 0ull;

    for (int chunk = 0; chunk < NCHUNK; ++chunk) {
        const int cur = chunk & 1;
        const int nxt = cur ^ 1;
        const bool has_next = (chunk + 1 < NCHUNK);

        float4 wreg[4];
        if (has_next) {
            // issue W LDG early (consumed after GEMM -> latency hidden)
            const float4* wg = (const float4*)(W1 + (size_t)(chunk + 1) * CK * HIDDEN);
            #pragma unroll
            for (int i = 0; i < 4; ++i) wreg[i] = wg[tid + i * THREADS];
            // stage next xs tile (MUFU work overlaps other warps' GEMM)
            stage_xs(chunk + 1, s_xs + nxt * (CK * ROWS));
        }

        // 256x64x64 SMEM GEMM on current buffers
        const float* xsc = s_xs + cur * (CK * ROWS);
        const float* wc  = s_w  + cur * (CK * HIDDEN);
        #pragma unroll 2
        for (int k = 0; k < CK; ++k) {
            const float* xb = xsc + k * ROWS + ty * 8;
            ulonglong2 xa = *(const ulonglong2*)(xb);
            ulonglong2 xc = *(const ulonglong2*)(xb + 4);
            unsigned long long xr[4] = { xa.x, xa.y, xc.x, xc.y };

            const float4* wb = (const float4*)(wc + k * HIDDEN + tx * 8);
            float4 w0 = wb[0], w1 = wb[1];
            unsigned long long wr[8] = {
                dup2(w0.x), dup2(w0.y), dup2(w0.z), dup2(w0.w),
                dup2(w1.x), dup2(w1.y), dup2(w1.z), dup2(w1.w)
            };
            #pragma unroll
            for (int c = 0; c < 8; ++c) {
                fma2(acc[0][c], xr[0], wr[c]);
                fma2(acc[1][c], xr[1], wr[c]);
                fma2(acc[2][c], xr[2], wr[c]);
                fma2(acc[3][c], xr[3], wr[c]);
            }
        }

        if (has_next) {
            // store prefetched W chunk (LDG has completed under the GEMM)
            float4* ws = (float4*)(s_w + nxt * (CK * HIDDEN));
            #pragma unroll
            for (int i = 0; i < 4; ++i) ws[tid + i * THREADS] = wreg[i];
        }
        __syncthreads();
    }

    // ---- stage W2 + epilogue ssp -> s_h ----
    for (int i = tid; i < HIDDEN * HIDDEN; i += THREADS) s_w[i] = W2[i];

    #pragma unroll
    for (int rp = 0; rp < 4; ++rp) {
        int r0 = ty * 8 + rp * 2;
        #pragma unroll
        for (int c = 0; c < 8; ++c) {
            int col = tx * 8 + c;
            unsigned long long v = acc[rp][c];
            float lo = __uint_as_float((unsigned)(v & 0xffffffffull));
            float hi = __uint_as_float((unsigned)(v >> 32));
            float bb = s_b1[col];
            s_h[(r0 + 0) * 66 + col] = sspf(lo + bb);
            s_h[(r0 + 1) * 66 + col] = sspf(hi + bb);
        }
    }
    __syncthreads();

    // ---- layer 2 (thread = row), layer 3, asymp ----
    float a2[HIDDEN];
    #pragma unroll
    for (int c = 0; c < HIDDEN; ++c) a2[c] = 0.0f;
    const float* hrow = s_h + tid * 66;
    #pragma unroll 2
    for (int k = 0; k < HIDDEN; ++k) {
        float a = hrow[k];
        const float4* w4 = (const float4*)(s_w + k * HIDDEN);
        #pragma unroll
        for (int j = 0; j < 16; ++j) {
            float4 w = w4[j];
            a2[4 * j + 0] += a * w.x;
            a2[4 * j + 1] += a * w.y;
            a2[4 * j + 2] += a * w.z;
            a2[4 * j + 3] += a * w.w;
        }
    }
    float partial = 0.0f;
    #pragma unroll
    for (int c = 0; c < HIDDEN; ++c)
        partial += sspf(a2[c] + s_b2[c]) * s_w3[c];
    float ys = partial + s_b3[0];

    float S = 0.0f;
    #pragma unroll 4
    for (int e = 0; e < N_EL; ++e) {
        float ex = myr[e * 3 + 0], ey = myr[e * 3 + 1], ez = myr[e * 3 + 2];
        #pragma unroll
        for (int a = 0; a < N_NUC; ++a) {
            float dx = ex - s_coord[a * 3 + 0];
            float dy = ey - s_coord[a * 3 + 1];
            float dz = ez - s_coord[a * 3 + 2];
            float d  = sqrtf(dx * dx + dy * dy + dz * dz);
            S += (s_chg[a] * d + d * d) / (1.0f + d);
        }
    }
    out[b0 + tid] = expf(ys) * expf(-S);
}

extern "C" void kernel_launch(void* const* d_in, const int* in_sizes, int n_in,
                              void* d_out, int out_size)
{
    const float* rs      = (const float*)d_in[0];
    const float* coords  = (const float*)d_in[1];
    const float* charges = (const float*)d_in[2];
    const float* W1      = (const float*)d_in[3];
    const float* b1      = (const float*)d_in[4];
    const float* W2      = (const float*)d_in[5];
    const float* b2      = (const float*)d_in[6];
    const float* W3      = (const float*)d_in[7];
    const float* b3      = (const float*)d_in[8];
    float* out = (float*)d_out;

    int batch = in_sizes[0] / (N_EL * 3);
    int grid  = batch / ROWS;

    cudaFuncSetAttribute(wfnet_kernel,
                         cudaFuncAttributeMaxDynamicSharedMemorySize, SMEM_BYTES);
    wfnet_kernel<<<grid, THREADS, SMEM_BYTES>>>(rs, coords, charges,
                                                W1, b1, W2, b2, W3, b3, out);
}

// round 10
// speedup vs baseline: 4.8503x; 1.6029x over previous
#include <cuda_runtime.h>
#include <cuda_bf16.h>
#include <math.h>
#include <stdint.h>

#define N_EL    16
#define N_NUC   4
#define N_FEATS 32
#define N_EN    64
#define N_EE    120
#define N_PAIRS 184
#define HIDDEN  64
#define ROWS    256
#define THREADS 256
#define CK      64
#define NCHUNK  92

// ---- SMEM layout (bytes) ----
#define ASTRIDE 144            // row stride of bf16 tiles (64 halves + 8 pad)
#define A_H     0              // 256 x 144 = 36864
#define A_L     36864
#define B_H     73728          // 64 x 144 = 9216
#define B_L     82944
#define OFF_RS  92160          // 256*49*4 = 50176
#define OFF_W2  73728          // overlay on B tiles after mainloop (16384)
#define OFF_H   0              // overlay on A tiles after mainloop (256*66*4)
#define OFF_ABC   142336       // 32 x float4
#define OFF_COORD 142848
#define OFF_CHG   142896
#define OFF_B1    142912
#define OFF_B2    143168
#define OFF_W3    143424
#define OFF_B3    143680
#define OFF_PI    143696
#define OFF_PJ    144176
#define SMEM_BYTES 144656

#define LOG2E 1.4426950408889634f

__device__ __forceinline__ float sspf(float x) {
    return fmaxf(x, 0.0f) + log1pf(expf(-fabsf(x))) - 0.69314718055994531f;
}
__device__ __forceinline__ float ex2(float x) {
    float r; asm("ex2.approx.ftz.f32 %0, %1;" : "=f"(r) : "f"(x)); return r;
}
__device__ __forceinline__ uint32_t smem_u32(const void* p) {
    uint32_t a;
    asm("{ .reg .u64 t; cvta.to.shared.u64 t, %1; cvt.u32.u64 %0, t; }"
        : "=r"(a) : "l"(p));
    return a;
}
__device__ __forceinline__ void ldsm4(uint32_t* r, uint32_t a) {
    asm volatile("ldmatrix.sync.aligned.m8n8.x4.shared.b16 {%0,%1,%2,%3}, [%4];"
        : "=r"(r[0]), "=r"(r[1]), "=r"(r[2]), "=r"(r[3]) : "r"(a));
}
__device__ __forceinline__ void ldsm4t(uint32_t* r, uint32_t a) {
    asm volatile("ldmatrix.sync.aligned.m8n8.x4.trans.shared.b16 {%0,%1,%2,%3}, [%4];"
        : "=r"(r[0]), "=r"(r[1]), "=r"(r[2]), "=r"(r[3]) : "r"(a));
}
__device__ __forceinline__ void mma16816(float* c, const uint32_t* a, const uint32_t* b) {
    asm volatile("mma.sync.aligned.m16n8k16.row.col.f32.bf16.bf16.f32 "
        "{%0,%1,%2,%3}, {%4,%5,%6,%7}, {%8,%9}, {%0,%1,%2,%3};"
        : "+f"(c[0]), "+f"(c[1]), "+f"(c[2]), "+f"(c[3])
        : "r"(a[0]), "r"(a[1]), "r"(a[2]), "r"(a[3]), "r"(b[0]), "r"(b[1]));
}
// hi = bf16-truncate of (a,b) packed; lo = rn-bf16 of residuals packed
__device__ __forceinline__ void pack_hilo(float a, float b, uint32_t& hp, uint32_t& lp) {
    uint32_t ua = __float_as_uint(a), ub = __float_as_uint(b);
    hp = __byte_perm(ua, ub, 0x7632);
    float ha = __uint_as_float(ua & 0xffff0000u);
    float hb = __uint_as_float(ub & 0xffff0000u);
    __nv_bfloat162 l2 = __floats2bfloat162_rn(a - ha, b - hb);
    lp = *reinterpret_cast<uint32_t*>(&l2);
}

__global__ __launch_bounds__(THREADS, 1)
void wfnet_kernel(const float* __restrict__ rs,
                  const float* __restrict__ coords,
                  const float* __restrict__ charges,
                  const float* __restrict__ W1,
                  const float* __restrict__ b1,
                  const float* __restrict__ W2,
                  const float* __restrict__ b2,
                  const float* __restrict__ W3,
                  const float* __restrict__ b3,
                  float* __restrict__ out)
{
    extern __shared__ char smem[];
    const uint32_t sbase = smem_u32(smem);

    float4* s_abc  = (float4*)(smem + OFF_ABC);
    float* s_coord = (float*)(smem + OFF_COORD);
    float* s_chg   = (float*)(smem + OFF_CHG);
    float* s_b1    = (float*)(smem + OFF_B1);
    float* s_b2    = (float*)(smem + OFF_B2);
    float* s_w3    = (float*)(smem + OFF_W3);
    float* s_b3    = (float*)(smem + OFF_B3);
    int*   s_pi    = (int*)  (smem + OFF_PI);
    int*   s_pj    = (int*)  (smem + OFF_PJ);
    float* s_rs    = (float*)(smem + OFF_RS);
    float* s_w2    = (float*)(smem + OFF_W2);
    float* s_h     = (float*)(smem + OFF_H);

    const int tid = threadIdx.x;
    const int b0  = blockIdx.x * ROWS;
    const int lane = tid & 31;
    const int warp = tid >> 5;

    // ---- setup ----
    if (tid < N_FEATS) {
        float q   = (float)tid / 31.0f;
        float mu  = 10.0f * q * q;
        float sig = (1.0f + 10.0f * q) * (1.0f / 7.0f);
        float a   = -LOG2E / (sig * sig);
        s_abc[tid] = make_float4(a, -2.0f * mu * a, a * mu * mu, 0.0f);
    }
    if (tid < 12) s_coord[tid] = coords[tid];
    if (tid < 4)  s_chg[tid]   = charges[tid];
    if (tid < HIDDEN) { s_b1[tid] = b1[tid]; s_b2[tid] = b2[tid]; s_w3[tid] = W3[tid]; }
    if (tid == 0) s_b3[0] = b3[0];
    if (tid < N_EE) {
        int rem = tid, i = 0, span = N_EL - 1;
        while (rem >= span) { rem -= span; span--; i++; }
        s_pi[tid] = i; s_pj[tid] = i + 1 + rem;
    }
    for (int idx = tid; idx < ROWS * 48; idx += THREADS) {
        int row = idx / 48, c = idx % 48;
        s_rs[row * 49 + c] = rs[(size_t)(b0 + row) * 48 + c];
    }
    __syncthreads();

    // ldmatrix lane address offsets (constant across chunks)
    const uint32_t aoff = A_H + (warp * 32 + (lane & 15)) * ASTRIDE + (lane >> 4) * 16;
    const uint32_t boff = B_H + (lane & 15) * ASTRIDE + (lane >> 4) * 16;

    float acc[2][8][4];
    #pragma unroll
    for (int mt = 0; mt < 2; ++mt)
        #pragma unroll
        for (int nt = 0; nt < 8; ++nt)
            #pragma unroll
            for (int q = 0; q < 4; ++q) acc[mt][nt][q] = 0.0f;

    for (int chunk = 0; chunk < NCHUNK; ++chunk) {
        // ---- prefetch W1 chunk rows (k = tid>>2, 16 n-values) ----
        float4 wv[4];
        {
            const float4* wrow = (const float4*)(W1
                + ((size_t)chunk * CK + (tid >> 2)) * HIDDEN + (tid & 3) * 16);
            #pragma unroll
            for (int i = 0; i < 4; ++i) wv[i] = wrow[i];
        }

        // ---- produce A tile: segment = 8 feats of (row, pair) ----
        #pragma unroll
        for (int i = 0; i < 8; ++i) {
            int s = tid + i * 256;
            int row = s >> 3, col8 = s & 7;
            const float* r = s_rs + row * 49;
            int p = chunk * 2 + (col8 >> 2);
            float dx, dy, dz;
            if (p < N_EN) {
                int e = p >> 2, a = p & 3;
                dx = r[e * 3 + 0] - s_coord[a * 3 + 0];
                dy = r[e * 3 + 1] - s_coord[a * 3 + 1];
                dz = r[e * 3 + 2] - s_coord[a * 3 + 2];
            } else {
                int q = p - N_EN;
                int ii = s_pi[q], jj = s_pj[q];
                dx = r[ii * 3 + 0] - r[jj * 3 + 0];
                dy = r[ii * 3 + 1] - r[jj * 3 + 1];
                dz = r[ii * 3 + 2] - r[jj * 3 + 2];
            }
            float d = sqrtf(dx * dx + dy * dy + dz * dz);

            int fb = (col8 & 3) * 8;
            float v[8];
            #pragma unroll
            for (int j = 0; j < 8; ++j) {
                float4 cc = s_abc[fb + j];
                v[j] = ex2(fmaf(fmaf(d, cc.x, cc.y), d, cc.z));
            }
            uint32_t hp[4], lp[4];
            #pragma unroll
            for (int t = 0; t < 4; ++t) pack_hilo(v[2 * t], v[2 * t + 1], hp[t], lp[t]);
            char* ap = smem + A_H + row * ASTRIDE + col8 * 16;
            *(uint4*)ap = make_uint4(hp[0], hp[1], hp[2], hp[3]);
            *(uint4*)(ap + (A_L - A_H)) = make_uint4(lp[0], lp[1], lp[2], lp[3]);
        }

        // ---- produce B tile [k][n] bf16 hi/lo ----
        {
            float vv[16] = { wv[0].x, wv[0].y, wv[0].z, wv[0].w,
                             wv[1].x, wv[1].y, wv[1].z, wv[1].w,
                             wv[2].x, wv[2].y, wv[2].z, wv[2].w,
                             wv[3].x, wv[3].y, wv[3].z, wv[3].w };
            uint32_t hp[8], lp[8];
            #pragma unroll
            for (int t = 0; t < 8; ++t) pack_hilo(vv[2 * t], vv[2 * t + 1], hp[t], lp[t]);
            char* bp = smem + B_H + (tid >> 2) * ASTRIDE + (tid & 3) * 32;
            *(uint4*)(bp)      = make_uint4(hp[0], hp[1], hp[2], hp[3]);
            *(uint4*)(bp + 16) = make_uint4(hp[4], hp[5], hp[6], hp[7]);
            *(uint4*)(bp + (B_L - B_H))      = make_uint4(lp[0], lp[1], lp[2], lp[3]);
            *(uint4*)(bp + (B_L - B_H) + 16) = make_uint4(lp[4], lp[5], lp[6], lp[7]);
        }
        __syncthreads();

        // ---- MMA: warp does rows warp*32..+32, all 64 cols, 3 terms ----
        #pragma unroll
        for (int ks = 0; ks < 4; ++ks) {
            uint32_t ah[2][4], al[2][4];
            ldsm4(ah[0], sbase + aoff + ks * 32);
            ldsm4(ah[1], sbase + aoff + 2304 + ks * 32);          // mt=1: +16*144
            ldsm4(al[0], sbase + aoff + (A_L - A_H) + ks * 32);
            ldsm4(al[1], sbase + aoff + (A_L - A_H) + 2304 + ks * 32);
            #pragma unroll
            for (int j = 0; j < 4; ++j) {
                uint32_t bh4[4], bl4[4];
                ldsm4t(bh4, sbase + boff + ks * 2304 + j * 32);
                ldsm4t(bl4, sbase + boff + (B_L - B_H) + ks * 2304 + j * 32);
                #pragma unroll
                for (int ht = 0; ht < 2; ++ht) {
                    #pragma unroll
                    for (int mt = 0; mt < 2; ++mt) {
                        mma16816(acc[mt][2 * j + ht], ah[mt], &bh4[2 * ht]);
                        mma16816(acc[mt][2 * j + ht], al[mt], &bh4[2 * ht]);
                        mma16816(acc[mt][2 * j + ht], ah[mt], &bl4[2 * ht]);
                    }
                }
            }
        }
        __syncthreads();
    }

    // ---- stage W2 (overlay on B region) ----
    {
        const float4* wg = (const float4*)W2;
        float4* ws = (float4*)s_w2;
        #pragma unroll
        for (int i = 0; i < 4; ++i) ws[tid + i * THREADS] = wg[tid + i * THREADS];
    }
    // ---- epilogue: ssp(acc + b1) -> s_h (overlay on A region, stride 66) ----
    #pragma unroll
    for (int mt = 0; mt < 2; ++mt) {
        #pragma unroll
        for (int nt = 0; nt < 8; ++nt) {
            int r0 = warp * 32 + mt * 16 + (lane >> 2);
            int c0 = nt * 8 + (lane & 3) * 2;
            s_h[r0 * 66 + c0]         = sspf(acc[mt][nt][0] + s_b1[c0]);
            s_h[r0 * 66 + c0 + 1]     = sspf(acc[mt][nt][1] + s_b1[c0 + 1]);
            s_h[(r0 + 8) * 66 + c0]     = sspf(acc[mt][nt][2] + s_b1[c0]);
            s_h[(r0 + 8) * 66 + c0 + 1] = sspf(acc[mt][nt][3] + s_b1[c0 + 1]);
        }
    }
    __syncthreads();

    // ---- layer 2 (thread = row), layer 3, asymp ----
    float a2[HIDDEN];
    #pragma unroll
    for (int c = 0; c < HIDDEN; ++c) a2[c] = 0.0f;
    const float* hrow = s_h + tid * 66;
    #pragma unroll 2
    for (int k = 0; k < HIDDEN; ++k) {
        float a = hrow[k];
        const float4* w4 = (const float4*)(s_w2 + k * HIDDEN);
        #pragma unroll
        for (int j = 0; j < 16; ++j) {
            float4 w = w4[j];
            a2[4 * j + 0] += a * w.x;
            a2[4 * j + 1] += a * w.y;
            a2[4 * j + 2] += a * w.z;
            a2[4 * j + 3] += a * w.w;
        }
    }
    float partial = 0.0f;
    #pragma unroll
    for (int c = 0; c < HIDDEN; ++c)
        partial += sspf(a2[c] + s_b2[c]) * s_w3[c];
    float ys = partial + s_b3[0];

    const float* myr = s_rs + tid * 49;
    float S = 0.0f;
    #pragma unroll 4
    for (int e = 0; e < N_EL; ++e) {
        float ex_ = myr[e * 3 + 0], ey = myr[e * 3 + 1], ez = myr[e * 3 + 2];
        #pragma unroll
        for (int a = 0; a < N_NUC; ++a) {
            float dx = ex_ - s_coord[a * 3 + 0];
            float dy = ey - s_coord[a * 3 + 1];
            float dz = ez - s_coord[a * 3 + 2];
            float dd = sqrtf(dx * dx + dy * dy + dz * dz);
            S += (s_chg[a] * dd + dd * dd) / (1.0f + dd);
        }
    }
    out[b0 + tid] = expf(ys) * expf(-S);
}

extern "C" void kernel_launch(void* const* d_in, const int* in_sizes, int n_in,
                              void* d_out, int out_size)
{
    const float* rs      = (const float*)d_in[0];
    const float* coords  = (const float*)d_in[1];
    const float* charges = (const float*)d_in[2];
    const float* W1      = (const float*)d_in[3];
    const float* b1      = (const float*)d_in[4];
    const float* W2      = (const float*)d_in[5];
    const float* b2      = (const float*)d_in[6];
    const float* W3      = (const float*)d_in[7];
    const float* b3      = (const float*)d_in[8];
    float* out = (float*)d_out;

    int batch = in_sizes[0] / (N_EL * 3);
    int grid  = batch / ROWS;

    cudaFuncSetAttribute(wfnet_kernel,
                         cudaFuncAttributeMaxDynamicSharedMemorySize, SMEM_BYTES);
    wfnet_kernel<<<grid, THREADS, SMEM_BYTES>>>(rs, coords, charges,
                                                W1, b1, W2, b2, W3, b3, out);
}

// round 11
// speedup vs baseline: 6.1356x; 1.2650x over previous
#include <cuda_runtime.h>
#include <cuda_bf16.h>
#include <math.h>
#include <stdint.h>

#define N_EL    16
#define N_NUC   4
#define N_FEATS 32
#define N_EN    64
#define N_EE    120
#define N_PAIRS 184
#define HIDDEN  64
#define ROWS    256
#define THREADS 256
#define CK      64
#define NCHUNK  92

// ---- SMEM layout (bytes) ----
// Each buffer: A_H 256x128, A_L 256x128, B_H 64x128, B_L 64x128 = 81920
#define BUFSZ   81920
#define A_Ho    0
#define A_Lo    32768
#define B_Ho    65536
#define B_Lo    73728
#define OFF_RS  163840             // 256*49*4 = 50176
#define OFF_W2  81920              // overlay on buf1 after mainloop (16384)
#define OFF_H   0                  // overlay on buf0 after mainloop (256*66*4)
#define OFF_ABC   214016
#define OFF_COORD 214528
#define OFF_CHG   214576
#define OFF_B1    214592
#define OFF_B2    214848
#define OFF_W3    215104
#define OFF_B3    215360
#define OFF_PI    215376
#define OFF_PJ    215856
#define SMEM_BYTES 216448

#define LOG2E 1.4426950408889634f

__device__ __forceinline__ float sspf(float x) {
    return fmaxf(x, 0.0f) + log1pf(expf(-fabsf(x))) - 0.69314718055994531f;
}
__device__ __forceinline__ float ex2(float x) {
    float r; asm("ex2.approx.ftz.f32 %0, %1;" : "=f"(r) : "f"(x)); return r;
}
__device__ __forceinline__ uint32_t smem_u32(const void* p) {
    uint32_t a;
    asm("{ .reg .u64 t; cvta.to.shared.u64 t, %1; cvt.u32.u64 %0, t; }"
        : "=r"(a) : "l"(p));
    return a;
}
__device__ __forceinline__ void ldsm4(uint32_t* r, uint32_t a) {
    asm volatile("ldmatrix.sync.aligned.m8n8.x4.shared.b16 {%0,%1,%2,%3}, [%4];"
        : "=r"(r[0]), "=r"(r[1]), "=r"(r[2]), "=r"(r[3]) : "r"(a));
}
__device__ __forceinline__ void ldsm4t(uint32_t* r, uint32_t a) {
    asm volatile("ldmatrix.sync.aligned.m8n8.x4.trans.shared.b16 {%0,%1,%2,%3}, [%4];"
        : "=r"(r[0]), "=r"(r[1]), "=r"(r[2]), "=r"(r[3]) : "r"(a));
}
__device__ __forceinline__ void mma16816(float* c, const uint32_t* a, const uint32_t* b) {
    asm volatile("mma.sync.aligned.m16n8k16.row.col.f32.bf16.bf16.f32 "
        "{%0,%1,%2,%3}, {%4,%5,%6,%7}, {%8,%9}, {%0,%1,%2,%3};"
        : "+f"(c[0]), "+f"(c[1]), "+f"(c[2]), "+f"(c[3])
        : "r"(a[0]), "r"(a[1]), "r"(a[2]), "r"(a[3]), "r"(b[0]), "r"(b[1]));
}
// hi = bf16-truncate of (a,b) packed; lo = rn-bf16 of residuals packed
__device__ __forceinline__ void pack_hilo(float a, float b, uint32_t& hp, uint32_t& lp) {
    uint32_t ua = __float_as_uint(a), ub = __float_as_uint(b);
    hp = __byte_perm(ua, ub, 0x7632);
    float ha = __uint_as_float(ua & 0xffff0000u);
    float hb = __uint_as_float(ub & 0xffff0000u);
    __nv_bfloat162 l2 = __floats2bfloat162_rn(a - ha, b - hb);
    lp = *reinterpret_cast<uint32_t*>(&l2);
}

__global__ __launch_bounds__(THREADS, 1)
void wfnet_kernel(const float* __restrict__ rs,
                  const float* __restrict__ coords,
                  const float* __restrict__ charges,
                  const float* __restrict__ W1,
                  const float* __restrict__ b1,
                  const float* __restrict__ W2,
                  const float* __restrict__ b2,
                  const float* __restrict__ W3,
                  const float* __restrict__ b3,
                  float* __restrict__ out)
{
    extern __shared__ char smem[];
    const uint32_t sbase = smem_u32(smem);

    float4* s_abc  = (float4*)(smem + OFF_ABC);
    float* s_coord = (float*)(smem + OFF_COORD);
    float* s_chg   = (float*)(smem + OFF_CHG);
    float* s_b1    = (float*)(smem + OFF_B1);
    float* s_b2    = (float*)(smem + OFF_B2);
    float* s_w3    = (float*)(smem + OFF_W3);
    float* s_b3    = (float*)(smem + OFF_B3);
    int*   s_pi    = (int*)  (smem + OFF_PI);
    int*   s_pj    = (int*)  (smem + OFF_PJ);
    float* s_rs    = (float*)(smem + OFF_RS);
    float* s_w2    = (float*)(smem + OFF_W2);
    float* s_h     = (float*)(smem + OFF_H);

    const int tid  = threadIdx.x;
    const int b0   = blockIdx.x * ROWS;
    const int lane = tid & 31;
    const int warp = tid >> 5;

    // ---- setup ----
    if (tid < N_FEATS) {
        float q   = (float)tid / 31.0f;
        float mu  = 10.0f * q * q;
        float sig = (1.0f + 10.0f * q) * (1.0f / 7.0f);
        float a   = -LOG2E / (sig * sig);
        s_abc[tid] = make_float4(a, -2.0f * mu * a, a * mu * mu, 0.0f);
    }
    if (tid < 12) s_coord[tid] = coords[tid];
    if (tid < 4)  s_chg[tid]   = charges[tid];
    if (tid < HIDDEN) { s_b1[tid] = b1[tid]; s_b2[tid] = b2[tid]; s_w3[tid] = W3[tid]; }
    if (tid == 0) s_b3[0] = b3[0];
    if (tid < N_EE) {
        int rem = tid, i = 0, span = N_EL - 1;
        while (rem >= span) { rem -= span; span--; i++; }
        s_pi[tid] = i; s_pj[tid] = i + 1 + rem;
    }
    for (int idx = tid; idx < ROWS * 48; idx += THREADS) {
        int row = idx / 48, c = idx % 48;
        s_rs[row * 49 + c] = rs[(size_t)(b0 + row) * 48 + c];
    }
    __syncthreads();

    const float* myr = s_rs + tid * 49;
    const int sw_t = tid & 7;                    // A producer swizzle key
    const int kB   = tid >> 2;                   // B producer: k row
    const int cB   = (tid & 3) * 2;              // B producer: col16 base
    const int swB  = kB & 7;

    // ---- producers (write chunk tiles into buffer bb) ----
    auto produceA = [&](int chunk, uint32_t bb) {
        float dpl[2];
        #pragma unroll
        for (int pl = 0; pl < 2; ++pl) {
            int p = chunk * 2 + pl;
            float dx, dy, dz;
            if (p < N_EN) {
                int e = p >> 2, a = p & 3;
                dx = myr[e * 3 + 0] - s_coord[a * 3 + 0];
                dy = myr[e * 3 + 1] - s_coord[a * 3 + 1];
                dz = myr[e * 3 + 2] - s_coord[a * 3 + 2];
            } else {
                int q = p - N_EN;
                int ii = s_pi[q], jj = s_pj[q];
                dx = myr[ii * 3 + 0] - myr[jj * 3 + 0];
                dy = myr[ii * 3 + 1] - myr[jj * 3 + 1];
                dz = myr[ii * 3 + 2] - myr[jj * 3 + 2];
            }
            dpl[pl] = sqrtf(dx * dx + dy * dy + dz * dz);
        }
        char* arow = smem + bb + A_Ho + tid * 128;
        #pragma unroll
        for (int g = 0; g < 8; ++g) {           // col16 group: g<4 pair0, else pair1
            float d  = dpl[g >> 2];
            int   fb = (g & 3) * 8;
            float v[8];
            #pragma unroll
            for (int j = 0; j < 8; ++j) {
                float4 cc = s_abc[fb + j];
                v[j] = ex2(fmaf(fmaf(d, cc.x, cc.y), d, cc.z));
            }
            uint32_t hp[4], lp[4];
            #pragma unroll
            for (int t = 0; t < 4; ++t) pack_hilo(v[2 * t], v[2 * t + 1], hp[t], lp[t]);
            uint32_t col = (uint32_t)((g ^ sw_t) << 4);
            *(uint4*)(arow + col) = make_uint4(hp[0], hp[1], hp[2], hp[3]);
            *(uint4*)(arow + (A_Lo - A_Ho) + col) = make_uint4(lp[0], lp[1], lp[2], lp[3]);
        }
    };
    auto produceB = [&](uint32_t bb, const float4* wv) {
        float vv[16] = { wv[0].x, wv[0].y, wv[0].z, wv[0].w,
                         wv[1].x, wv[1].y, wv[1].z, wv[1].w,
                         wv[2].x, wv[2].y, wv[2].z, wv[2].w,
                         wv[3].x, wv[3].y, wv[3].z, wv[3].w };
        uint32_t hp[8], lp[8];
        #pragma unroll
        for (int t = 0; t < 8; ++t) pack_hilo(vv[2 * t], vv[2 * t + 1], hp[t], lp[t]);
        char* brow = smem + bb + B_Ho + kB * 128;
        uint32_t c0 = (uint32_t)((cB ^ swB) << 4);
        uint32_t c1 = (uint32_t)(((cB + 1) ^ swB) << 4);
        *(uint4*)(brow + c0) = make_uint4(hp[0], hp[1], hp[2], hp[3]);
        *(uint4*)(brow + c1) = make_uint4(hp[4], hp[5], hp[6], hp[7]);
        *(uint4*)(brow + (B_Lo - B_Ho) + c0) = make_uint4(lp[0], lp[1], lp[2], lp[3]);
        *(uint4*)(brow + (B_Lo - B_Ho) + c1) = make_uint4(lp[4], lp[5], lp[6], lp[7]);
    };

    // ldmatrix per-lane constants
    const int sw_l = lane & 7;
    const int hi4  = lane >> 4;
    const uint32_t arow_l = (uint32_t)((warp * 32 + (lane & 15)) * 128);
    const uint32_t brow_l = (uint32_t)((lane & 15) * 128);

    float acc[2][8][4];
    #pragma unroll
    for (int mt = 0; mt < 2; ++mt)
        #pragma unroll
        for (int nt = 0; nt < 8; ++nt)
            #pragma unroll
            for (int q = 0; q < 4; ++q) acc[mt][nt][q] = 0.0f;

    // ---- prologue: produce chunk 0 into buf0 ----
    {
        float4 wv[4];
        const float4* wrow = (const float4*)(W1 + (size_t)kB * HIDDEN + (tid & 3) * 16);
        #pragma unroll
        for (int i = 0; i < 4; ++i) wv[i] = wrow[i];
        produceA(0, 0);
        produceB(0, wv);
    }
    __syncthreads();

    // ---- mainloop: one barrier per chunk, produce next while MMA current ----
    for (int chunk = 0; chunk < NCHUNK; ++chunk) {
        const uint32_t bbc = (uint32_t)(chunk & 1) * BUFSZ;
        const uint32_t bbn = bbc ^ BUFSZ;

        if (chunk + 1 < NCHUNK) {
            // issue W LDG first; consumed after A production (latency hidden)
            float4 wv[4];
            const float4* wrow = (const float4*)(W1
                + ((size_t)(chunk + 1) * CK + kB) * HIDDEN + (tid & 3) * 16);
            #pragma unroll
            for (int i = 0; i < 4; ++i) wv[i] = wrow[i];
            produceA(chunk + 1, bbn);
            produceB(bbn, wv);
        }

        // ---- MMA on current buffer ----
        const uint32_t abase = sbase + bbc + A_Ho + arow_l;
        const uint32_t bbase = sbase + bbc + B_Ho + brow_l;
        #pragma unroll
        for (int ks = 0; ks < 4; ++ks) {
            uint32_t ac = (uint32_t)(((2 * ks + hi4) ^ sw_l) << 4);
            uint32_t ah[2][4], al[2][4];
            ldsm4(ah[0], abase + ac);
            ldsm4(ah[1], abase + 2048 + ac);
            ldsm4(al[0], abase + (A_Lo - A_Ho) + ac);
            ldsm4(al[1], abase + (A_Lo - A_Ho) + 2048 + ac);
            #pragma unroll
            for (int j = 0; j < 4; ++j) {
                uint32_t bc = (uint32_t)(((2 * j + hi4) ^ sw_l) << 4);
                uint32_t bh4[4], bl4[4];
                ldsm4t(bh4, bbase + ks * 2048 + bc);
                ldsm4t(bl4, bbase + (B_Lo - B_Ho) + ks * 2048 + bc);
                #pragma unroll
                for (int ht = 0; ht < 2; ++ht) {
                    #pragma unroll
                    for (int mt = 0; mt < 2; ++mt) {
                        mma16816(acc[mt][2 * j + ht], ah[mt], &bh4[2 * ht]);
                        mma16816(acc[mt][2 * j + ht], al[mt], &bh4[2 * ht]);
                        mma16816(acc[mt][2 * j + ht], ah[mt], &bl4[2 * ht]);
                    }
                }
            }
        }
        __syncthreads();
    }

    // ---- stage W2 (overlay buf1) + epilogue ssp(acc+b1) -> s_h (overlay buf0) ----
    {
        const float4* wg = (const float4*)W2;
        float4* ws = (float4*)s_w2;
        #pragma unroll
        for (int i = 0; i < 4; ++i) ws[tid + i * THREADS] = wg[tid + i * THREADS];
    }
    #pragma unroll
    for (int mt = 0; mt < 2; ++mt) {
        #pragma unroll
        for (int nt = 0; nt < 8; ++nt) {
            int r0 = warp * 32 + mt * 16 + (lane >> 2);
            int c0 = nt * 8 + (lane & 3) * 2;
            s_h[r0 * 66 + c0]           = sspf(acc[mt][nt][0] + s_b1[c0]);
            s_h[r0 * 66 + c0 + 1]       = sspf(acc[mt][nt][1] + s_b1[c0 + 1]);
            s_h[(r0 + 8) * 66 + c0]     = sspf(acc[mt][nt][2] + s_b1[c0]);
            s_h[(r0 + 8) * 66 + c0 + 1] = sspf(acc[mt][nt][3] + s_b1[c0 + 1]);
        }
    }
    __syncthreads();

    // ---- layer 2 (thread = row), layer 3, asymp ----
    float a2[HIDDEN];
    #pragma unroll
    for (int c = 0; c < HIDDEN; ++c) a2[c] = 0.0f;
    const float* hrow = s_h + tid * 66;
    #pragma unroll 2
    for (int k = 0; k < HIDDEN; ++k) {
        float a = hrow[k];
        const float4* w4 = (const float4*)(s_w2 + k * HIDDEN);
        #pragma unroll
        for (int j = 0; j < 16; ++j) {
            float4 w = w4[j];
            a2[4 * j + 0] += a * w.x;
            a2[4 * j + 1] += a * w.y;
            a2[4 * j + 2] += a * w.z;
            a2[4 * j + 3] += a * w.w;
        }
    }
    float partial = 0.0f;
    #pragma unroll
    for (int c = 0; c < HIDDEN; ++c)
        partial += sspf(a2[c] + s_b2[c]) * s_w3[c];
    float ys = partial + s_b3[0];

    float S = 0.0f;
    #pragma unroll 4
    for (int e = 0; e < N_EL; ++e) {
        float ex_ = myr[e * 3 + 0], ey = myr[e * 3 + 1], ez = myr[e * 3 + 2];
        #pragma unroll
        for (int a = 0; a < N_NUC; ++a) {
            float dx = ex_ - s_coord[a * 3 + 0];
            float dy = ey - s_coord[a * 3 + 1];
            float dz = ez - s_coord[a * 3 + 2];
            float dd = sqrtf(dx * dx + dy * dy + dz * dz);
            S += (s_chg[a] * dd + dd * dd) / (1.0f + dd);
        }
    }
    out[b0 + tid] = expf(ys) * expf(-S);
}

extern "C" void kernel_launch(void* const* d_in, const int* in_sizes, int n_in,
                              void* d_out, int out_size)
{
    const float* rs      = (const float*)d_in[0];
    const float* coords  = (const float*)d_in[1];
    const float* charges = (const float*)d_in[2];
    const float* W1      = (const float*)d_in[3];
    const float* b1      = (const float*)d_in[4];
    const float* W2      = (const float*)d_in[5];
    const float* b2      = (const float*)d_in[6];
    const float* W3      = (const float*)d_in[7];
    const float* b3      = (const float*)d_in[8];
    float* out = (float*)d_out;

    int batch = in_sizes[0] / (N_EL * 3);
    int grid  = batch / ROWS;

    cudaFuncSetAttribute(wfnet_kernel,
                         cudaFuncAttributeMaxDynamicSharedMemorySize, SMEM_BYTES);
    wfnet_kernel<<<grid, THREADS, SMEM_BYTES>>>(rs, coords, charges,
                                                W1, b1, W2, b2, W3, b3, out);
}